// round 1
// baseline (speedup 1.0000x reference)
#include <cuda_runtime.h>
#include <cuda_bf16.h>
#include <cstdint>

// Problem constants
#define B_ 4
#define S_ 2048
#define D_ 1024
#define H_ 16
#define DK_ 64
#define M_ (B_ * S_)   // 8192

// Scratch: projected Q,K,V in [B,H,S,DK] layout + attention output in [B,S,D]
__device__ float g_Q[(size_t)M_ * D_];
__device__ float g_K[(size_t)M_ * D_];
__device__ float g_V[(size_t)M_ * D_];
__device__ float g_A[(size_t)M_ * D_];

// ---------------------------------------------------------------------------
// 128x128x8 tiled SGEMM: C = A[M,K] * W[K,N] + bias, optional head-layout write
// head_mode=1: out[((b*H+h)*S+s)*DK+dk] = (acc+bias)*scale  (m=b*S+s, n=h*DK+dk)
// head_mode=0: out[m*N+n] = acc + bias
// ---------------------------------------------------------------------------
__global__ __launch_bounds__(256)
void sgemm128(const float* __restrict__ A, const float* __restrict__ W,
              const float* __restrict__ bias, float* __restrict__ C,
              int M, int N, int K, int head_mode, float scale)
{
    __shared__ float As[8][128];
    __shared__ float Bs[8][128];

    const int tid = threadIdx.x;
    const int m0 = blockIdx.y * 128;
    const int n0 = blockIdx.x * 128;
    const int tx = tid & 15;        // 16 thread cols
    const int ty = tid >> 4;        // 16 thread rows

    float acc[8][8];
    #pragma unroll
    for (int i = 0; i < 8; i++)
        #pragma unroll
        for (int j = 0; j < 8; j++) acc[i][j] = 0.f;

    const int arow = tid >> 1;          // 0..127
    const int acol = (tid & 1) << 2;    // 0 or 4
    const int brow = tid >> 5;          // 0..7
    const int bcol = (tid & 31) << 2;   // 0..124

    const float* Aptr = A + (size_t)(m0 + arow) * K + acol;
    const float* Wptr = W + (size_t)brow * N + n0 + bcol;

    for (int kt = 0; kt < K; kt += 8) {
        float4 av = *(const float4*)(Aptr + kt);
        float4 bv = *(const float4*)(Wptr + (size_t)kt * N);
        As[acol + 0][arow] = av.x;
        As[acol + 1][arow] = av.y;
        As[acol + 2][arow] = av.z;
        As[acol + 3][arow] = av.w;
        *(float4*)&Bs[brow][bcol] = bv;
        __syncthreads();

        #pragma unroll
        for (int kk = 0; kk < 8; kk++) {
            float ra[8], rb[8];
            *(float4*)&ra[0] = *(const float4*)&As[kk][ty * 8 + 0];
            *(float4*)&ra[4] = *(const float4*)&As[kk][ty * 8 + 4];
            *(float4*)&rb[0] = *(const float4*)&Bs[kk][tx * 8 + 0];
            *(float4*)&rb[4] = *(const float4*)&Bs[kk][tx * 8 + 4];
            #pragma unroll
            for (int i = 0; i < 8; i++)
                #pragma unroll
                for (int j = 0; j < 8; j++)
                    acc[i][j] += ra[i] * rb[j];
        }
        __syncthreads();
    }

    // Epilogue
    #pragma unroll
    for (int i = 0; i < 8; i++) {
        const int m = m0 + ty * 8 + i;
        #pragma unroll
        for (int j = 0; j < 8; j++) {
            const int n = n0 + tx * 8 + j;
            float v = acc[i][j] + bias[n];
            if (head_mode) {
                v *= scale;
                const int b = m >> 11;        // /S_ (2048)
                const int s = m & (S_ - 1);
                const int h = n >> 6;         // /DK_
                const int dk = n & (DK_ - 1);
                C[((size_t)((b << 4) + h) * S_ + s) * DK_ + dk] = v;
            } else {
                C[(size_t)m * N + n] = v;
            }
        }
    }
}

// ---------------------------------------------------------------------------
// Flash attention: one query row per thread, 128 queries per block.
// Online softmax with per-tile (32 keys) score staging in SMEM so max-rescale
// of the o-accumulator happens once per tile, not per key.
// Q is pre-scaled by 1/sqrt(DK) in the projection epilogue.
// ---------------------------------------------------------------------------
__global__ __launch_bounds__(128)
void attn_kernel(const float* __restrict__ Qh, const float* __restrict__ Kh,
                 const float* __restrict__ Vh, float* __restrict__ O)
{
    __shared__ float Ks[32][64];
    __shared__ float Vs[32][64];
    __shared__ float Sc[128][33];   // +1 pad -> conflict-free per-thread rows

    const int tid = threadIdx.x;
    const int bh = blockIdx.y;          // b*H + h
    const int b  = bh >> 4;
    const int h  = bh & (H_ - 1);
    const int qrow = blockIdx.x * 128 + tid;

    const float* qptr = Qh + ((size_t)bh * S_ + qrow) * DK_;
    float4 q4[16];
    #pragma unroll
    for (int d = 0; d < 16; d++) q4[d] = ((const float4*)qptr)[d];

    float4 o4[16];
    #pragma unroll
    for (int d = 0; d < 16; d++) o4[d] = make_float4(0.f, 0.f, 0.f, 0.f);

    float mmax = -1e30f, lsum = 0.f;

    const float* kbase = Kh + (size_t)bh * S_ * DK_;
    const float* vbase = Vh + (size_t)bh * S_ * DK_;

    for (int kt = 0; kt < S_; kt += 32) {
        __syncthreads();
        // Cooperative load: 32 keys x 64 dims = 512 float4, 4 per thread
        #pragma unroll
        for (int i = 0; i < 4; i++) {
            const int idx = i * 128 + tid;
            const int r = idx >> 4;       // key row
            const int c = idx & 15;       // float4 col
            ((float4*)&Ks[r][0])[c] = ((const float4*)(kbase + (size_t)(kt + r) * DK_))[c];
            ((float4*)&Vs[r][0])[c] = ((const float4*)(vbase + (size_t)(kt + r) * DK_))[c];
        }
        __syncthreads();

        // Pass 1: scores into SMEM, track tile max
        float tmax = -1e30f;
        #pragma unroll 4
        for (int j = 0; j < 32; j++) {
            float s = 0.f;
            #pragma unroll
            for (int d = 0; d < 16; d++) {
                const float4 kv = ((const float4*)&Ks[j][0])[d];
                s += q4[d].x * kv.x + q4[d].y * kv.y + q4[d].z * kv.z + q4[d].w * kv.w;
            }
            Sc[tid][j] = s;
            tmax = fmaxf(tmax, s);
        }

        // One rescale per tile
        const float mnew = fmaxf(mmax, tmax);
        const float f = __expf(mmax - mnew);
        lsum *= f;
        #pragma unroll
        for (int d = 0; d < 16; d++) {
            o4[d].x *= f; o4[d].y *= f; o4[d].z *= f; o4[d].w *= f;
        }
        mmax = mnew;

        // Pass 2: exp + V accumulate
        #pragma unroll 2
        for (int j = 0; j < 32; j++) {
            const float p = __expf(Sc[tid][j] - mmax);
            lsum += p;
            #pragma unroll
            for (int d = 0; d < 16; d++) {
                const float4 vv = ((const float4*)&Vs[j][0])[d];
                o4[d].x += p * vv.x; o4[d].y += p * vv.y;
                o4[d].z += p * vv.z; o4[d].w += p * vv.w;
            }
        }
    }

    const float inv = 1.f / lsum;
    float* optr = O + ((size_t)b * S_ + qrow) * D_ + h * DK_;
    #pragma unroll
    for (int d = 0; d < 16; d++) {
        float4 ov;
        ov.x = o4[d].x * inv; ov.y = o4[d].y * inv;
        ov.z = o4[d].z * inv; ov.w = o4[d].w * inv;
        ((float4*)optr)[d] = ov;
    }
}

// ---------------------------------------------------------------------------
extern "C" void kernel_launch(void* const* d_in, const int* in_sizes, int n_in,
                              void* d_out, int out_size)
{
    const float* q  = (const float*)d_in[0];
    const float* k  = (const float*)d_in[1];
    const float* v  = (const float*)d_in[2];
    const float* wq = (const float*)d_in[3];
    const float* bq = (const float*)d_in[4];
    const float* wk = (const float*)d_in[5];
    const float* bk = (const float*)d_in[6];
    const float* wv = (const float*)d_in[7];
    const float* bv = (const float*)d_in[8];
    const float* wo = (const float*)d_in[9];
    const float* bo = (const float*)d_in[10];
    float* out = (float*)d_out;

    float *Qs, *Ks, *Vs, *As;
    cudaGetSymbolAddress((void**)&Qs, g_Q);
    cudaGetSymbolAddress((void**)&Ks, g_K);
    cudaGetSymbolAddress((void**)&Vs, g_V);
    cudaGetSymbolAddress((void**)&As, g_A);

    dim3 gemm_grid(D_ / 128, M_ / 128);   // (8, 64)

    // Projections (Q pre-scaled by 1/sqrt(DK) = 0.125)
    sgemm128<<<gemm_grid, 256>>>(q, wq, bq, Qs, M_, D_, D_, 1, 0.125f);
    sgemm128<<<gemm_grid, 256>>>(k, wk, bk, Ks, M_, D_, D_, 1, 1.0f);
    sgemm128<<<gemm_grid, 256>>>(v, wv, bv, Vs, M_, D_, D_, 1, 1.0f);

    // Attention: 16 q-tiles x 64 (b,h) pairs
    attn_kernel<<<dim3(S_ / 128, B_ * H_), 128>>>(Qs, Ks, Vs, As);

    // Output projection -> d_out
    sgemm128<<<gemm_grid, 256>>>(As, wo, bo, out, M_, D_, D_, 0, 1.0f);
}

// round 2
// speedup vs baseline: 4.3662x; 4.3662x over previous
#include <cuda_runtime.h>
#include <cuda_bf16.h>
#include <cstdint>

#define B_ 4
#define S_ 2048
#define D_ 1024
#define H_ 16
#define DK_ 64
#define M_ (B_ * S_)   // 8192

// Scratch: projected Q,K,V in [B,H,S,DK] layout + attention output in [B,S,D]
__device__ float g_Q[(size_t)M_ * D_];
__device__ float g_K[(size_t)M_ * D_];
__device__ float g_V[(size_t)M_ * D_];
__device__ float g_A[(size_t)M_ * D_];

// ---------------------------------------------------------------------------
// tf32 helpers
// ---------------------------------------------------------------------------
__device__ __forceinline__ uint32_t f2tf(float x) {
    uint32_t u;
    asm("cvt.rna.tf32.f32 %0, %1;" : "=r"(u) : "f"(x));
    return u;
}

__device__ __forceinline__ void mma_tf32(float c[4], const uint32_t a[4], const uint32_t b[2]) {
    asm volatile(
        "mma.sync.aligned.m16n8k8.row.col.f32.tf32.tf32.f32 "
        "{%0,%1,%2,%3}, {%4,%5,%6,%7}, {%8,%9}, {%0,%1,%2,%3};\n"
        : "+f"(c[0]), "+f"(c[1]), "+f"(c[2]), "+f"(c[3])
        : "r"(a[0]), "r"(a[1]), "r"(a[2]), "r"(a[3]), "r"(b[0]), "r"(b[1]));
}

// ---------------------------------------------------------------------------
// tf32 tensor-core GEMM: C[M,N] = A[M,K] * W[K,N] + bias
// BM=128 BN=128 BK=16, 8 warps, warp tile 64x32 (4 m-tiles x 4 n-tiles m16n8k8)
// head_mode=1: scatter to [B,H,S,DK] layout with scale.
// ---------------------------------------------------------------------------
#define PADA 20     // conflict-free A-fragment loads (bank = 20*g + t distinct)
#define PADB 136    // conflict-free B-fragment loads (bank = 8*k + g distinct)

__global__ __launch_bounds__(256)
void gemm_tf32(const float* __restrict__ A, const float* __restrict__ W,
               const float* __restrict__ bias, float* __restrict__ C,
               int head_mode, float scale)
{
    const int K = D_, N = D_;
    __shared__ uint32_t As[2][128 * PADA];
    __shared__ uint32_t Bs[2][16 * PADB];

    const int tid  = threadIdx.x;
    const int lane = tid & 31;
    const int warp = tid >> 5;
    const int wm = warp & 1;      // 2 warp rows
    const int wn = warp >> 1;     // 4 warp cols
    const int m0 = blockIdx.y * 128;
    const int n0 = blockIdx.x * 128;

    float acc[4][4][4];
    #pragma unroll
    for (int mt = 0; mt < 4; mt++)
        #pragma unroll
        for (int nt = 0; nt < 4; nt++)
            #pragma unroll
            for (int c = 0; c < 4; c++) acc[mt][nt][c] = 0.f;

    const int rA = tid >> 2, cA = tid & 3;     // A: 128 rows x 4 float4 cols
    const int rB = tid >> 5, cB = tid & 31;    // B: 16 rows x 32 float4 cols

    float4 pa[2], pb[2];

    // prologue: chunk 0
    #pragma unroll
    for (int i = 0; i < 2; i++) {
        pa[i] = *(const float4*)(A + (size_t)(m0 + rA + 64 * i) * K + 4 * cA);
        pb[i] = *(const float4*)(W + (size_t)(rB + 8 * i) * N + n0 + 4 * cB);
    }
    #pragma unroll
    for (int i = 0; i < 2; i++) {
        uint32_t* p = &As[0][(rA + 64 * i) * PADA + 4 * cA];
        p[0] = f2tf(pa[i].x); p[1] = f2tf(pa[i].y); p[2] = f2tf(pa[i].z); p[3] = f2tf(pa[i].w);
        uint32_t* q = &Bs[0][(rB + 8 * i) * PADB + 4 * cB];
        q[0] = f2tf(pb[i].x); q[1] = f2tf(pb[i].y); q[2] = f2tf(pb[i].z); q[3] = f2tf(pb[i].w);
    }
    __syncthreads();

    const int NKT = K / 16;   // 64
    for (int kt = 0; kt < NKT; kt++) {
        const int buf = kt & 1;
        if (kt + 1 < NKT) {
            const int kn = (kt + 1) * 16;
            #pragma unroll
            for (int i = 0; i < 2; i++) {
                pa[i] = *(const float4*)(A + (size_t)(m0 + rA + 64 * i) * K + kn + 4 * cA);
                pb[i] = *(const float4*)(W + (size_t)(kn + rB + 8 * i) * N + n0 + 4 * cB);
            }
        }

        #pragma unroll
        for (int ks = 0; ks < 2; ks++) {
            uint32_t af[4][4], bf[4][2];
            #pragma unroll
            for (int mt = 0; mt < 4; mt++) {
                const int row = wm * 64 + mt * 16 + (lane >> 2);
                const int col = ks * 8 + (lane & 3);
                const uint32_t* base = &As[buf][0];
                af[mt][0] = base[row * PADA + col];
                af[mt][1] = base[(row + 8) * PADA + col];
                af[mt][2] = base[row * PADA + col + 4];
                af[mt][3] = base[(row + 8) * PADA + col + 4];
            }
            #pragma unroll
            for (int nt = 0; nt < 4; nt++) {
                const int kk = ks * 8 + (lane & 3);
                const int nn = wn * 32 + nt * 8 + (lane >> 2);
                bf[nt][0] = Bs[buf][kk * PADB + nn];
                bf[nt][1] = Bs[buf][(kk + 4) * PADB + nn];
            }
            #pragma unroll
            for (int mt = 0; mt < 4; mt++)
                #pragma unroll
                for (int nt = 0; nt < 4; nt++)
                    mma_tf32(acc[mt][nt], af[mt], bf[nt]);
        }

        if (kt + 1 < NKT) {
            #pragma unroll
            for (int i = 0; i < 2; i++) {
                uint32_t* p = &As[buf ^ 1][(rA + 64 * i) * PADA + 4 * cA];
                p[0] = f2tf(pa[i].x); p[1] = f2tf(pa[i].y); p[2] = f2tf(pa[i].z); p[3] = f2tf(pa[i].w);
                uint32_t* q = &Bs[buf ^ 1][(rB + 8 * i) * PADB + 4 * cB];
                q[0] = f2tf(pb[i].x); q[1] = f2tf(pb[i].y); q[2] = f2tf(pb[i].z); q[3] = f2tf(pb[i].w);
            }
        }
        __syncthreads();
    }

    // epilogue
    #pragma unroll
    for (int mt = 0; mt < 4; mt++) {
        #pragma unroll
        for (int nt = 0; nt < 4; nt++) {
            #pragma unroll
            for (int c = 0; c < 4; c++) {
                const int m = m0 + wm * 64 + mt * 16 + (lane >> 2) + ((c & 2) ? 8 : 0);
                const int n = n0 + wn * 32 + nt * 8 + 2 * (lane & 3) + (c & 1);
                float v = acc[mt][nt][c] + bias[n];
                if (head_mode) {
                    v *= scale;
                    const int b  = m >> 11;
                    const int s  = m & (S_ - 1);
                    const int h  = n >> 6;
                    const int dk = n & (DK_ - 1);
                    C[((size_t)((b << 4) + h) * S_ + s) * DK_ + dk] = v;
                } else {
                    C[(size_t)m * N + n] = v;
                }
            }
        }
    }
}

// ---------------------------------------------------------------------------
// Flash attention with tf32 mma: 64 q-rows per block (4 warps x 16 rows),
// key tiles of 64. QK^T and PV on tensor cores; online softmax in fragments.
// P round-trips through the K SMEM buffer (safe: K fully consumed first).
// ---------------------------------------------------------------------------
#define PKP 68   // K/P buffer pad: frag bank = 4*key + dk -> distinct
#define PVV 72   // V buffer pad: frag bank = 8*(lane&3) + (lane>>2) -> distinct

__global__ __launch_bounds__(128)
void attn_tf32(const float* __restrict__ Qh, const float* __restrict__ Kh,
               const float* __restrict__ Vh, float* __restrict__ O)
{
    __shared__ uint32_t KPs[64 * PKP];
    __shared__ uint32_t Vs[64 * PVV];

    const int tid  = threadIdx.x;
    const int lane = tid & 31;
    const int warp = tid >> 5;
    const int bh = blockIdx.y;
    const int b  = bh >> 4;
    const int h  = bh & (H_ - 1);
    const int q0 = blockIdx.x * 64;
    const int wrow = warp * 16;

    const int fr = lane >> 2;     // fragment row within 8-group
    const int fc = lane & 3;      // fragment col within 4-group

    // Q fragments (warp's 16 rows x 64 dk), loaded once. Q pre-scaled by 1/8.
    uint32_t qa[8][4];
    {
        const float* qb = Qh + ((size_t)bh * S_ + q0 + wrow) * DK_;
        #pragma unroll
        for (int ks = 0; ks < 8; ks++) {
            qa[ks][0] = f2tf(qb[(size_t)fr * DK_ + ks * 8 + fc]);
            qa[ks][1] = f2tf(qb[(size_t)(fr + 8) * DK_ + ks * 8 + fc]);
            qa[ks][2] = f2tf(qb[(size_t)fr * DK_ + ks * 8 + fc + 4]);
            qa[ks][3] = f2tf(qb[(size_t)(fr + 8) * DK_ + ks * 8 + fc + 4]);
        }
    }

    float oacc[8][4];
    #pragma unroll
    for (int nt = 0; nt < 8; nt++)
        #pragma unroll
        for (int c = 0; c < 4; c++) oacc[nt][c] = 0.f;

    float m0v = -1e30f, m1v = -1e30f, l0 = 0.f, l1 = 0.f;

    const float* kb = Kh + (size_t)bh * S_ * DK_;
    const float* vb = Vh + (size_t)bh * S_ * DK_;

    for (int t = 0; t < S_; t += 64) {
        __syncthreads();   // prior PV reads of KPs/Vs complete
        #pragma unroll
        for (int i = 0; i < 8; i++) {
            const int idx = i * 128 + tid;
            const int r = idx >> 4, c4 = idx & 15;
            float4 kv = *(const float4*)(kb + (size_t)(t + r) * DK_ + 4 * c4);
            float4 vv = *(const float4*)(vb + (size_t)(t + r) * DK_ + 4 * c4);
            uint32_t* kp = &KPs[r * PKP + 4 * c4];
            kp[0] = f2tf(kv.x); kp[1] = f2tf(kv.y); kp[2] = f2tf(kv.z); kp[3] = f2tf(kv.w);
            uint32_t* vp = &Vs[r * PVV + 4 * c4];
            vp[0] = f2tf(vv.x); vp[1] = f2tf(vv.y); vp[2] = f2tf(vv.z); vp[3] = f2tf(vv.w);
        }
        __syncthreads();

        // S = Q K^T  (16 rows x 64 keys per warp)
        float sacc[8][4];
        #pragma unroll
        for (int nt = 0; nt < 8; nt++)
            #pragma unroll
            for (int c = 0; c < 4; c++) sacc[nt][c] = 0.f;

        #pragma unroll
        for (int ks = 0; ks < 8; ks++) {
            #pragma unroll
            for (int nt = 0; nt < 8; nt++) {
                uint32_t bf[2];
                const int key = nt * 8 + fr;
                const int dk  = ks * 8 + fc;
                bf[0] = KPs[key * PKP + dk];
                bf[1] = KPs[key * PKP + dk + 4];
                mma_tf32(sacc[nt], qa[ks], bf);
            }
        }

        // online softmax
        float rmax0 = -1e30f, rmax1 = -1e30f;
        #pragma unroll
        for (int nt = 0; nt < 8; nt++) {
            rmax0 = fmaxf(rmax0, fmaxf(sacc[nt][0], sacc[nt][1]));
            rmax1 = fmaxf(rmax1, fmaxf(sacc[nt][2], sacc[nt][3]));
        }
        #pragma unroll
        for (int off = 1; off < 4; off <<= 1) {
            rmax0 = fmaxf(rmax0, __shfl_xor_sync(0xffffffffu, rmax0, off));
            rmax1 = fmaxf(rmax1, __shfl_xor_sync(0xffffffffu, rmax1, off));
        }
        const float mn0 = fmaxf(m0v, rmax0);
        const float mn1 = fmaxf(m1v, rmax1);
        const float f0 = __expf(m0v - mn0);
        const float f1 = __expf(m1v - mn1);
        m0v = mn0; m1v = mn1;

        float rs0 = 0.f, rs1 = 0.f;
        #pragma unroll
        for (int nt = 0; nt < 8; nt++) {
            sacc[nt][0] = __expf(sacc[nt][0] - m0v); rs0 += sacc[nt][0];
            sacc[nt][1] = __expf(sacc[nt][1] - m0v); rs0 += sacc[nt][1];
            sacc[nt][2] = __expf(sacc[nt][2] - m1v); rs1 += sacc[nt][2];
            sacc[nt][3] = __expf(sacc[nt][3] - m1v); rs1 += sacc[nt][3];
        }
        #pragma unroll
        for (int off = 1; off < 4; off <<= 1) {
            rs0 += __shfl_xor_sync(0xffffffffu, rs0, off);
            rs1 += __shfl_xor_sync(0xffffffffu, rs1, off);
        }
        l0 = l0 * f0 + rs0;
        l1 = l1 * f1 + rs1;
        #pragma unroll
        for (int nt = 0; nt < 8; nt++) {
            oacc[nt][0] *= f0; oacc[nt][1] *= f0;
            oacc[nt][2] *= f1; oacc[nt][3] *= f1;
        }

        __syncthreads();   // all warps finished reading K from KPs

        // store P (tf32) into KPs, warp-private rows
        {
            const int cc = 2 * fc;
            #pragma unroll
            for (int nt = 0; nt < 8; nt++) {
                uint2 v0 = make_uint2(f2tf(sacc[nt][0]), f2tf(sacc[nt][1]));
                *(uint2*)&KPs[(wrow + fr) * PKP + nt * 8 + cc] = v0;
                uint2 v1 = make_uint2(f2tf(sacc[nt][2]), f2tf(sacc[nt][3]));
                *(uint2*)&KPs[(wrow + fr + 8) * PKP + nt * 8 + cc] = v1;
            }
        }
        __syncwarp();

        // O += P V   (A = P from KPs, B = V from Vs)
        #pragma unroll
        for (int ks = 0; ks < 8; ks++) {
            uint32_t af[4];
            af[0] = KPs[(wrow + fr) * PKP + ks * 8 + fc];
            af[1] = KPs[(wrow + fr + 8) * PKP + ks * 8 + fc];
            af[2] = KPs[(wrow + fr) * PKP + ks * 8 + fc + 4];
            af[3] = KPs[(wrow + fr + 8) * PKP + ks * 8 + fc + 4];
            #pragma unroll
            for (int nt = 0; nt < 8; nt++) {
                uint32_t bf[2];
                const int key = ks * 8 + fc;
                const int dk  = nt * 8 + fr;
                bf[0] = Vs[key * PVV + dk];
                bf[1] = Vs[(key + 4) * PVV + dk];
                mma_tf32(oacc[nt], af, bf);
            }
        }
    }

    // normalize + write [B,S,D] layout
    const float inv0 = 1.f / l0;
    const float inv1 = 1.f / l1;
    float* ob = O + ((size_t)b * S_ + q0 + wrow) * D_ + h * DK_;
    const int cc = 2 * fc;
    #pragma unroll
    for (int nt = 0; nt < 8; nt++) {
        float2 v0 = make_float2(oacc[nt][0] * inv0, oacc[nt][1] * inv0);
        *(float2*)&ob[(size_t)fr * D_ + nt * 8 + cc] = v0;
        float2 v1 = make_float2(oacc[nt][2] * inv1, oacc[nt][3] * inv1);
        *(float2*)&ob[(size_t)(fr + 8) * D_ + nt * 8 + cc] = v1;
    }
}

// ---------------------------------------------------------------------------
extern "C" void kernel_launch(void* const* d_in, const int* in_sizes, int n_in,
                              void* d_out, int out_size)
{
    const float* q  = (const float*)d_in[0];
    const float* k  = (const float*)d_in[1];
    const float* v  = (const float*)d_in[2];
    const float* wq = (const float*)d_in[3];
    const float* bq = (const float*)d_in[4];
    const float* wk = (const float*)d_in[5];
    const float* bk = (const float*)d_in[6];
    const float* wv = (const float*)d_in[7];
    const float* bv = (const float*)d_in[8];
    const float* wo = (const float*)d_in[9];
    const float* bo = (const float*)d_in[10];
    float* out = (float*)d_out;

    float *Qs, *Ks, *Vs, *As;
    cudaGetSymbolAddress((void**)&Qs, g_Q);
    cudaGetSymbolAddress((void**)&Ks, g_K);
    cudaGetSymbolAddress((void**)&Vs, g_V);
    cudaGetSymbolAddress((void**)&As, g_A);

    dim3 gemm_grid(D_ / 128, M_ / 128);   // (8, 64)

    gemm_tf32<<<gemm_grid, 256>>>(q, wq, bq, Qs, 1, 0.125f);
    gemm_tf32<<<gemm_grid, 256>>>(k, wk, bk, Ks, 1, 1.0f);
    gemm_tf32<<<gemm_grid, 256>>>(v, wv, bv, Vs, 1, 1.0f);

    attn_tf32<<<dim3(S_ / 64, B_ * H_), 128>>>(Qs, Ks, Vs, As);

    gemm_tf32<<<gemm_grid, 256>>>(As, wo, bo, out, 0, 1.0f);
}

// round 6
// speedup vs baseline: 8.8819x; 2.0342x over previous
#include <cuda_runtime.h>
#include <cuda_fp16.h>
#include <cstdint>

#define B_ 4
#define S_ 2048
#define D_ 1024
#define H_ 16
#define DK_ 64
#define M_ (B_ * S_)   // 8192

// Scratch (half precision: these feed fp16 mma anyway)
__device__ __half g_Qh[(size_t)M_ * D_];
__device__ __half g_Kh[(size_t)M_ * D_];
__device__ __half g_Vh[(size_t)M_ * D_];
__device__ __half g_Ah[(size_t)M_ * D_];
__device__ __half g_WTh[4][(size_t)D_ * D_];   // transposed half weights [N,K]

// ---------------------------------------------------------------------------
// helpers
// ---------------------------------------------------------------------------
__device__ __forceinline__ uint32_t smem_u32(const void* p) {
    uint32_t a;
    asm("{ .reg .u64 t; cvta.to.shared.u64 t, %1; cvt.u32.u64 %0, t; }" : "=r"(a) : "l"(p));
    return a;
}
__device__ __forceinline__ uint32_t pack2(float a, float b) {
    __half2 h = __floats2half2_rn(a, b);
    return *(uint32_t*)&h;
}
__device__ __forceinline__ void ldm_x4(uint32_t r[4], uint32_t addr) {
    asm volatile("ldmatrix.sync.aligned.m8n8.x4.shared.b16 {%0,%1,%2,%3}, [%4];"
                 : "=r"(r[0]), "=r"(r[1]), "=r"(r[2]), "=r"(r[3]) : "r"(addr));
}
__device__ __forceinline__ void ldm_x4_t(uint32_t r[4], uint32_t addr) {
    asm volatile("ldmatrix.sync.aligned.m8n8.x4.trans.shared.b16 {%0,%1,%2,%3}, [%4];"
                 : "=r"(r[0]), "=r"(r[1]), "=r"(r[2]), "=r"(r[3]) : "r"(addr));
}
__device__ __forceinline__ void mma16816(float c[4], const uint32_t a[4],
                                         uint32_t b0, uint32_t b1) {
    asm volatile(
        "mma.sync.aligned.m16n8k16.row.col.f32.f16.f16.f32 "
        "{%0,%1,%2,%3}, {%4,%5,%6,%7}, {%8,%9}, {%0,%1,%2,%3};\n"
        : "+f"(c[0]), "+f"(c[1]), "+f"(c[2]), "+f"(c[3])
        : "r"(a[0]), "r"(a[1]), "r"(a[2]), "r"(a[3]), "r"(b0), "r"(b1));
}

// ---------------------------------------------------------------------------
// Weight transpose + fp16 convert: out[n*1024+k] = (half)in[k*1024+n]
// ---------------------------------------------------------------------------
__global__ __launch_bounds__(256)
void transposeWh(const float* __restrict__ in, __half* __restrict__ out)
{
    __shared__ float t[32][33];
    const int bx = blockIdx.x * 32, by = blockIdx.y * 32;
    const int tx = threadIdx.x & 31, ty = threadIdx.x >> 5;
    #pragma unroll
    for (int i = 0; i < 32; i += 8)
        t[ty + i][tx] = in[(size_t)(by + ty + i) * D_ + bx + tx];
    __syncthreads();
    #pragma unroll
    for (int i = 0; i < 32; i += 8)
        out[(size_t)(bx + ty + i) * D_ + by + tx] = __float2half_rn(t[tx][ty + i]);
}

// ---------------------------------------------------------------------------
// fp16 tensor-core GEMM: C[M,N] = A[M,K] * Wt[N,K]^T + bias
// BM=128 BN=128 BK=32, 8 warps (warp tile 64x32), double-buffered SMEM,
// ldmatrix fragment loads. AHALF: A operand already half in gmem.
// HEADOUT: scatter half result to [B,H,S,DK] with scale; else float [M,N].
// ---------------------------------------------------------------------------
#define ASTR 40   // SMEM row stride in halves (conflict-free for ldmatrix.x4)
#define NKT  (D_ / 32)

template<bool AHALF, bool HEADOUT>
__global__ __launch_bounds__(256)
void gemm_fp16(const void* __restrict__ Av, const __half* __restrict__ Wt,
               const float* __restrict__ bias, void* __restrict__ Cv, float scale)
{
    __shared__ __align__(16) __half As[2][128 * ASTR];
    __shared__ __align__(16) __half Bs[2][128 * ASTR];

    const int tid  = threadIdx.x;
    const int lane = tid & 31;
    const int warp = tid >> 5;
    const int wm = warp & 1;      // 2 warp rows (64 each)
    const int wn = warp >> 1;     // 4 warp cols (32 each)
    const int m0 = blockIdx.y * 128;
    const int n0 = blockIdx.x * 128;

    float acc[4][4][4];
    #pragma unroll
    for (int mt = 0; mt < 4; mt++)
        #pragma unroll
        for (int nt = 0; nt < 4; nt++)
            #pragma unroll
            for (int c = 0; c < 4; c++) acc[mt][nt][c] = 0.f;

    // ldmatrix per-lane address components
    const int rowA = wm * 64 + ((lane >> 3) & 1) * 8 + (lane & 7);
    const int cbA  = lane >> 4;            // chunk bit for A
    const int rowB = wn * 32 + (lane >> 4) * 8 + (lane & 7);
    const int cbB  = (lane >> 3) & 1;      // chunk bit for B

    // prefetch registers
    float4 pa[4]; uint4 pah[2]; uint4 pb[2];

    // ---- load / store macros (manual inline) ----
    #define LOAD_A(k0)                                                          \
        if (AHALF) {                                                            \
            _Pragma("unroll")                                                   \
            for (int q = 0; q < 2; q++) {                                       \
                const int idx = q * 256 + tid;                                  \
                const int r = idx >> 2, c8 = idx & 3;                           \
                pah[q] = *(const uint4*)((const __half*)Av +                    \
                          (size_t)(m0 + r) * D_ + (k0) + 8 * c8);               \
            }                                                                   \
        } else {                                                                \
            _Pragma("unroll")                                                   \
            for (int q = 0; q < 4; q++) {                                       \
                const int idx = q * 256 + tid;                                  \
                const int r = idx >> 3, c = idx & 7;                            \
                pa[q] = *(const float4*)((const float*)Av +                     \
                          (size_t)(m0 + r) * D_ + (k0) + 4 * c);                \
            }                                                                   \
        }
    #define LOAD_B(k0)                                                          \
        _Pragma("unroll")                                                       \
        for (int q = 0; q < 2; q++) {                                           \
            const int idx = q * 256 + tid;                                      \
            const int r = idx >> 2, c8 = idx & 3;                               \
            pb[q] = *(const uint4*)(Wt + (size_t)(n0 + r) * D_ + (k0) + 8 * c8);\
        }
    #define STORE_AB(buf)                                                       \
        if (AHALF) {                                                            \
            _Pragma("unroll")                                                   \
            for (int q = 0; q < 2; q++) {                                       \
                const int idx = q * 256 + tid;                                  \
                const int r = idx >> 2, c8 = idx & 3;                           \
                *(uint4*)&As[buf][r * ASTR + 8 * c8] = pah[q];                  \
            }                                                                   \
        } else {                                                                \
            _Pragma("unroll")                                                   \
            for (int q = 0; q < 4; q++) {                                       \
                const int idx = q * 256 + tid;                                  \
                const int r = idx >> 3, c = idx & 7;                            \
                uint2 u = make_uint2(pack2(pa[q].x, pa[q].y),                   \
                                     pack2(pa[q].z, pa[q].w));                  \
                *(uint2*)&As[buf][r * ASTR + 4 * c] = u;                        \
            }                                                                   \
        }                                                                       \
        _Pragma("unroll")                                                       \
        for (int q = 0; q < 2; q++) {                                           \
            const int idx = q * 256 + tid;                                      \
            const int r = idx >> 2, c8 = idx & 3;                               \
            *(uint4*)&Bs[buf][r * ASTR + 8 * c8] = pb[q];                       \
        }

    LOAD_A(0); LOAD_B(0); STORE_AB(0);
    __syncthreads();

    const uint32_t aBase0 = smem_u32(&As[0][0]);
    const uint32_t bBase0 = smem_u32(&Bs[0][0]);
    const uint32_t bufStride = 128 * ASTR * 2;   // bytes

    for (int kt = 0; kt < NKT; kt++) {
        const int buf = kt & 1;
        if (kt + 1 < NKT) { const int kn = (kt + 1) * 32; LOAD_A(kn); LOAD_B(kn); }

        const uint32_t aB = aBase0 + buf * bufStride;
        const uint32_t bB = bBase0 + buf * bufStride;

        #pragma unroll
        for (int ks = 0; ks < 2; ks++) {
            uint32_t af[4][4];
            #pragma unroll
            for (int mt = 0; mt < 4; mt++)
                ldm_x4(af[mt], aB + 2 * ((rowA + mt * 16) * ASTR + (2 * ks + cbA) * 8));
            #pragma unroll
            for (int g = 0; g < 2; g++) {
                uint32_t bf[4];
                ldm_x4(bf, bB + 2 * ((rowB + g * 16) * ASTR + (2 * ks + cbB) * 8));
                #pragma unroll
                for (int mt = 0; mt < 4; mt++) {
                    mma16816(acc[mt][2 * g],     af[mt], bf[0], bf[1]);
                    mma16816(acc[mt][2 * g + 1], af[mt], bf[2], bf[3]);
                }
            }
        }

        if (kt + 1 < NKT) { STORE_AB(buf ^ 1); }
        __syncthreads();
    }

    // epilogue
    const int fr = lane >> 2;
    const int fc = lane & 3;
    #pragma unroll
    for (int mt = 0; mt < 4; mt++) {
        #pragma unroll
        for (int nt = 0; nt < 4; nt++) {
            const int n = n0 + wn * 32 + nt * 8 + 2 * fc;
            const float b0 = bias[n], b1 = bias[n + 1];
            #pragma unroll
            for (int half_ : {0, 1}) {
                const int m = m0 + wm * 64 + mt * 16 + fr + half_ * 8;
                const float v0 = acc[mt][nt][2 * half_ + 0] + b0;
                const float v1 = acc[mt][nt][2 * half_ + 1] + b1;
                if (HEADOUT) {
                    const int b  = m >> 11;
                    const int s  = m & (S_ - 1);
                    const int h  = n >> 6;
                    const int dk = n & (DK_ - 1);
                    __half2 hv = __floats2half2_rn(v0 * scale, v1 * scale);
                    *(__half2*)((__half*)Cv +
                        ((size_t)((b << 4) + h) * S_ + s) * DK_ + dk) = hv;
                } else {
                    *(float2*)((float*)Cv + (size_t)m * D_ + n) = make_float2(v0, v1);
                }
            }
        }
    }
    #undef LOAD_A
    #undef LOAD_B
    #undef STORE_AB
}

// ---------------------------------------------------------------------------
// fp16 flash attention: 64 q-rows/block (4 warps x 16), 64-key tiles.
// ldmatrix for K (non-trans) and V (trans); P stays in registers.
// Q pre-scaled by 1/8 in projection.
// ---------------------------------------------------------------------------
#define KSTR 72   // SMEM row stride in halves

__global__ __launch_bounds__(128)
void attn_fp16(const __half* __restrict__ Qh, const __half* __restrict__ Kh,
               const __half* __restrict__ Vh, __half* __restrict__ O)
{
    __shared__ __align__(16) __half Ks[64 * KSTR];
    __shared__ __align__(16) __half Vs[64 * KSTR];

    const int tid  = threadIdx.x;
    const int lane = tid & 31;
    const int warp = tid >> 5;
    const int bh = blockIdx.y;
    const int b  = bh >> 4;
    const int h  = bh & (H_ - 1);
    const int q0 = blockIdx.x * 64;
    const int wrow = warp * 16;

    const int fr = lane >> 2;
    const int fc = lane & 3;

    // Q fragments: warp's 16 rows x 64 dk, 4 k-steps of 16
    uint32_t qa[4][4];
    {
        const __half* qb = Qh + ((size_t)bh * S_ + q0 + wrow) * DK_;
        #pragma unroll
        for (int ks = 0; ks < 4; ks++) {
            qa[ks][0] = *(const uint32_t*)(qb + (size_t)fr * DK_ + ks * 16 + 2 * fc);
            qa[ks][1] = *(const uint32_t*)(qb + (size_t)(fr + 8) * DK_ + ks * 16 + 2 * fc);
            qa[ks][2] = *(const uint32_t*)(qb + (size_t)fr * DK_ + ks * 16 + 2 * fc + 8);
            qa[ks][3] = *(const uint32_t*)(qb + (size_t)(fr + 8) * DK_ + ks * 16 + 2 * fc + 8);
        }
    }

    float oacc[8][4];
    #pragma unroll
    for (int nt = 0; nt < 8; nt++)
        #pragma unroll
        for (int c = 0; c < 4; c++) oacc[nt][c] = 0.f;

    float m0v = -1e30f, m1v = -1e30f, l0 = 0.f, l1 = 0.f;

    const __half* kb = Kh + (size_t)bh * S_ * DK_;
    const __half* vb = Vh + (size_t)bh * S_ * DK_;

    const uint32_t ksBase = smem_u32(Ks);
    const uint32_t vsBase = smem_u32(Vs);
    // ldmatrix per-lane address components
    const int rowK = (lane >> 4) * 8 + (lane & 7);
    const int cbK  = (lane >> 3) & 1;
    const int rowV = ((lane >> 3) & 1) * 8 + (lane & 7);
    const int cbV  = lane >> 4;

    for (int t = 0; t < S_; t += 64) {
        __syncthreads();   // previous tile's PV reads complete
        #pragma unroll
        for (int i = 0; i < 4; i++) {
            const int idx = i * 128 + tid;
            const int r = idx >> 3, c8 = idx & 7;
            *(uint4*)&Ks[r * KSTR + 8 * c8] =
                *(const uint4*)(kb + (size_t)(t + r) * DK_ + 8 * c8);
            *(uint4*)&Vs[r * KSTR + 8 * c8] =
                *(const uint4*)(vb + (size_t)(t + r) * DK_ + 8 * c8);
        }
        __syncthreads();

        // S = Q K^T  (16 rows x 64 keys per warp)
        float sacc[8][4];
        #pragma unroll
        for (int nt = 0; nt < 8; nt++)
            #pragma unroll
            for (int c = 0; c < 4; c++) sacc[nt][c] = 0.f;

        #pragma unroll
        for (int ks = 0; ks < 4; ks++) {
            #pragma unroll
            for (int g = 0; g < 4; g++) {
                uint32_t bf[4];
                ldm_x4(bf, ksBase + 2 * ((g * 16 + rowK) * KSTR + (2 * ks + cbK) * 8));
                mma16816(sacc[2 * g],     qa[ks], bf[0], bf[1]);
                mma16816(sacc[2 * g + 1], qa[ks], bf[2], bf[3]);
            }
        }

        // online softmax (fp32)
        float rmax0 = -1e30f, rmax1 = -1e30f;
        #pragma unroll
        for (int nt = 0; nt < 8; nt++) {
            rmax0 = fmaxf(rmax0, fmaxf(sacc[nt][0], sacc[nt][1]));
            rmax1 = fmaxf(rmax1, fmaxf(sacc[nt][2], sacc[nt][3]));
        }
        #pragma unroll
        for (int off = 1; off < 4; off <<= 1) {
            rmax0 = fmaxf(rmax0, __shfl_xor_sync(0xffffffffu, rmax0, off));
            rmax1 = fmaxf(rmax1, __shfl_xor_sync(0xffffffffu, rmax1, off));
        }
        const float mn0 = fmaxf(m0v, rmax0);
        const float mn1 = fmaxf(m1v, rmax1);
        const float f0 = __expf(m0v - mn0);
        const float f1 = __expf(m1v - mn1);
        m0v = mn0; m1v = mn1;

        float rs0 = 0.f, rs1 = 0.f;
        #pragma unroll
        for (int nt = 0; nt < 8; nt++) {
            sacc[nt][0] = __expf(sacc[nt][0] - m0v); rs0 += sacc[nt][0];
            sacc[nt][1] = __expf(sacc[nt][1] - m0v); rs0 += sacc[nt][1];
            sacc[nt][2] = __expf(sacc[nt][2] - m1v); rs1 += sacc[nt][2];
            sacc[nt][3] = __expf(sacc[nt][3] - m1v); rs1 += sacc[nt][3];
        }
        #pragma unroll
        for (int off = 1; off < 4; off <<= 1) {
            rs0 += __shfl_xor_sync(0xffffffffu, rs0, off);
            rs1 += __shfl_xor_sync(0xffffffffu, rs1, off);
        }
        l0 = l0 * f0 + rs0;
        l1 = l1 * f1 + rs1;
        #pragma unroll
        for (int nt = 0; nt < 8; nt++) {
            oacc[nt][0] *= f0; oacc[nt][1] *= f0;
            oacc[nt][2] *= f1; oacc[nt][3] *= f1;
        }

        // O += P V : P directly from accumulator registers (no SMEM round-trip)
        #pragma unroll
        for (int ks = 0; ks < 4; ks++) {
            uint32_t pf[4];
            pf[0] = pack2(sacc[2 * ks][0],     sacc[2 * ks][1]);
            pf[1] = pack2(sacc[2 * ks][2],     sacc[2 * ks][3]);
            pf[2] = pack2(sacc[2 * ks + 1][0], sacc[2 * ks + 1][1]);
            pf[3] = pack2(sacc[2 * ks + 1][2], sacc[2 * ks + 1][3]);
            #pragma unroll
            for (int gp = 0; gp < 4; gp++) {
                uint32_t bf[4];
                ldm_x4_t(bf, vsBase + 2 * ((ks * 16 + rowV) * KSTR + (2 * gp + cbV) * 8));
                mma16816(oacc[2 * gp],     pf, bf[0], bf[1]);
                mma16816(oacc[2 * gp + 1], pf, bf[2], bf[3]);
            }
        }
    }

    // normalize + write half [B,S,D]
    const float inv0 = 1.f / l0;
    const float inv1 = 1.f / l1;
    __half* ob = O + ((size_t)b * S_ + q0 + wrow) * D_ + h * DK_;
    #pragma unroll
    for (int nt = 0; nt < 8; nt++) {
        *(__half2*)(ob + (size_t)fr * D_ + nt * 8 + 2 * fc) =
            __floats2half2_rn(oacc[nt][0] * inv0, oacc[nt][1] * inv0);
        *(__half2*)(ob + (size_t)(fr + 8) * D_ + nt * 8 + 2 * fc) =
            __floats2half2_rn(oacc[nt][2] * inv1, oacc[nt][3] * inv1);
    }
}

// ---------------------------------------------------------------------------
extern "C" void kernel_launch(void* const* d_in, const int* in_sizes, int n_in,
                              void* d_out, int out_size)
{
    const float* q  = (const float*)d_in[0];
    const float* k  = (const float*)d_in[1];
    const float* v  = (const float*)d_in[2];
    const float* wq = (const float*)d_in[3];
    const float* bq = (const float*)d_in[4];
    const float* wk = (const float*)d_in[5];
    const float* bk = (const float*)d_in[6];
    const float* wv = (const float*)d_in[7];
    const float* bv = (const float*)d_in[8];
    const float* wo = (const float*)d_in[9];
    const float* bo = (const float*)d_in[10];
    float* out = (float*)d_out;

    __half *Qs, *Ks, *Vs, *As, *WT;
    cudaGetSymbolAddress((void**)&Qs, g_Qh);
    cudaGetSymbolAddress((void**)&Ks, g_Kh);
    cudaGetSymbolAddress((void**)&Vs, g_Vh);
    cudaGetSymbolAddress((void**)&As, g_Ah);
    cudaGetSymbolAddress((void**)&WT, g_WTh);
    __half* WqT = WT + 0 * (size_t)D_ * D_;
    __half* WkT = WT + 1 * (size_t)D_ * D_;
    __half* WvT = WT + 2 * (size_t)D_ * D_;
    __half* WoT = WT + 3 * (size_t)D_ * D_;

    dim3 tgrid(32, 32);
    transposeWh<<<tgrid, 256>>>(wq, WqT);
    transposeWh<<<tgrid, 256>>>(wk, WkT);
    transposeWh<<<tgrid, 256>>>(wv, WvT);
    transposeWh<<<tgrid, 256>>>(wo, WoT);

    dim3 ggrid(D_ / 128, M_ / 128);   // (8, 64)
    gemm_fp16<false, true><<<ggrid, 256>>>(q, WqT, bq, Qs, 0.125f);
    gemm_fp16<false, true><<<ggrid, 256>>>(k, WkT, bk, Ks, 1.0f);
    gemm_fp16<false, true><<<ggrid, 256>>>(v, WvT, bv, Vs, 1.0f);

    attn_fp16<<<dim3(S_ / 64, B_ * H_), 128>>>(Qs, Ks, Vs, As);

    gemm_fp16<true, false><<<ggrid, 256>>>(As, WoT, bo, out, 1.0f);
}

// round 7
// speedup vs baseline: 9.5741x; 1.0779x over previous
#include <cuda_runtime.h>
#include <cuda_fp16.h>
#include <cstdint>

#define B_ 4
#define S_ 2048
#define D_ 1024
#define H_ 16
#define DK_ 64
#define M_ (B_ * S_)   // 8192

// Q pre-scale: (1/sqrt(64)) * log2(e)  -> scores in log2 domain
#define QSCALE 0.18033688011112042f

// Scratch (half precision)
__device__ __half g_Qh[(size_t)M_ * D_];
__device__ __half g_Kh[(size_t)M_ * D_];
__device__ __half g_Vh[(size_t)M_ * D_];
__device__ __half g_Ah[(size_t)M_ * D_];
__device__ __half g_WTh[4][(size_t)D_ * D_];   // transposed half weights [N,K]

// ---------------------------------------------------------------------------
// helpers
// ---------------------------------------------------------------------------
__device__ __forceinline__ uint32_t smem_u32(const void* p) {
    uint32_t a;
    asm("{ .reg .u64 t; cvta.to.shared.u64 t, %1; cvt.u32.u64 %0, t; }" : "=r"(a) : "l"(p));
    return a;
}
__device__ __forceinline__ uint32_t pack2(float a, float b) {
    __half2 h = __floats2half2_rn(a, b);
    return *(uint32_t*)&h;
}
__device__ __forceinline__ void ldm_x4(uint32_t r[4], uint32_t addr) {
    asm volatile("ldmatrix.sync.aligned.m8n8.x4.shared.b16 {%0,%1,%2,%3}, [%4];"
                 : "=r"(r[0]), "=r"(r[1]), "=r"(r[2]), "=r"(r[3]) : "r"(addr));
}
__device__ __forceinline__ void ldm_x4_t(uint32_t r[4], uint32_t addr) {
    asm volatile("ldmatrix.sync.aligned.m8n8.x4.trans.shared.b16 {%0,%1,%2,%3}, [%4];"
                 : "=r"(r[0]), "=r"(r[1]), "=r"(r[2]), "=r"(r[3]) : "r"(addr));
}
__device__ __forceinline__ void mma16816(float c[4], const uint32_t a[4],
                                         uint32_t b0, uint32_t b1) {
    asm volatile(
        "mma.sync.aligned.m16n8k16.row.col.f32.f16.f16.f32 "
        "{%0,%1,%2,%3}, {%4,%5,%6,%7}, {%8,%9}, {%0,%1,%2,%3};\n"
        : "+f"(c[0]), "+f"(c[1]), "+f"(c[2]), "+f"(c[3])
        : "r"(a[0]), "r"(a[1]), "r"(a[2]), "r"(a[3]), "r"(b0), "r"(b1));
}
#define CP_ASYNC16(dst, src) \
    asm volatile("cp.async.cg.shared.global [%0], [%1], 16;" :: "r"(dst), "l"(src))
#define CP_COMMIT()  asm volatile("cp.async.commit_group;" ::: "memory")
#define CP_WAIT0()   asm volatile("cp.async.wait_group 0;" ::: "memory")
#define CP_WAIT1()   asm volatile("cp.async.wait_group 1;" ::: "memory")

// ---------------------------------------------------------------------------
// Merged weight transpose + fp16 convert (all 4 weights, one launch)
// ---------------------------------------------------------------------------
struct WPtrs { const float* in[4]; __half* out[4]; };

__global__ __launch_bounds__(256)
void transposeWh4(WPtrs p)
{
    __shared__ float t[32][33];
    const float* in = p.in[blockIdx.z];
    __half* out = p.out[blockIdx.z];
    const int bx = blockIdx.x * 32, by = blockIdx.y * 32;
    const int tx = threadIdx.x & 31, ty = threadIdx.x >> 5;
    #pragma unroll
    for (int i = 0; i < 32; i += 8)
        t[ty + i][tx] = in[(size_t)(by + ty + i) * D_ + bx + tx];
    __syncthreads();
    #pragma unroll
    for (int i = 0; i < 32; i += 8)
        out[(size_t)(bx + ty + i) * D_ + by + tx] = __float2half_rn(t[tx][ty + i]);
}

// ---------------------------------------------------------------------------
// fp16 GEMM core (BM=128 BN=128 BK=32, 8 warps, double-buffered SMEM)
// ---------------------------------------------------------------------------
#define ASTR 40
#define NKT  (D_ / 32)

template<bool AHALF, bool HEADOUT>
__device__ __forceinline__
void gemm_body(const void* __restrict__ Av, const __half* __restrict__ Wt,
               const float* __restrict__ bias, void* __restrict__ Cv,
               float scale, int m0, int n0)
{
    __shared__ __align__(16) __half As[2][128 * ASTR];
    __shared__ __align__(16) __half Bs[2][128 * ASTR];

    const int tid  = threadIdx.x;
    const int lane = tid & 31;
    const int warp = tid >> 5;
    const int wm = warp & 1;
    const int wn = warp >> 1;

    float acc[4][4][4];
    #pragma unroll
    for (int mt = 0; mt < 4; mt++)
        #pragma unroll
        for (int nt = 0; nt < 4; nt++)
            #pragma unroll
            for (int c = 0; c < 4; c++) acc[mt][nt][c] = 0.f;

    const int rowA = wm * 64 + ((lane >> 3) & 1) * 8 + (lane & 7);
    const int cbA  = lane >> 4;
    const int rowB = wn * 32 + (lane >> 4) * 8 + (lane & 7);
    const int cbB  = (lane >> 3) & 1;

    float4 pa[4]; uint4 pah[2]; uint4 pb[2];

    #define LOAD_A(k0)                                                          \
        if (AHALF) {                                                            \
            _Pragma("unroll")                                                   \
            for (int q = 0; q < 2; q++) {                                       \
                const int idx = q * 256 + tid;                                  \
                const int r = idx >> 2, c8 = idx & 3;                           \
                pah[q] = *(const uint4*)((const __half*)Av +                    \
                          (size_t)(m0 + r) * D_ + (k0) + 8 * c8);               \
            }                                                                   \
        } else {                                                                \
            _Pragma("unroll")                                                   \
            for (int q = 0; q < 4; q++) {                                       \
                const int idx = q * 256 + tid;                                  \
                const int r = idx >> 3, c = idx & 7;                            \
                pa[q] = *(const float4*)((const float*)Av +                     \
                          (size_t)(m0 + r) * D_ + (k0) + 4 * c);                \
            }                                                                   \
        }
    #define LOAD_B(k0)                                                          \
        _Pragma("unroll")                                                       \
        for (int q = 0; q < 2; q++) {                                           \
            const int idx = q * 256 + tid;                                      \
            const int r = idx >> 2, c8 = idx & 3;                               \
            pb[q] = *(const uint4*)(Wt + (size_t)(n0 + r) * D_ + (k0) + 8 * c8);\
        }
    #define STORE_AB(buf)                                                       \
        if (AHALF) {                                                            \
            _Pragma("unroll")                                                   \
            for (int q = 0; q < 2; q++) {                                       \
                const int idx = q * 256 + tid;                                  \
                const int r = idx >> 2, c8 = idx & 3;                           \
                *(uint4*)&As[buf][r * ASTR + 8 * c8] = pah[q];                  \
            }                                                                   \
        } else {                                                                \
            _Pragma("unroll")                                                   \
            for (int q = 0; q < 4; q++) {                                       \
                const int idx = q * 256 + tid;                                  \
                const int r = idx >> 3, c = idx & 7;                            \
                uint2 u = make_uint2(pack2(pa[q].x, pa[q].y),                   \
                                     pack2(pa[q].z, pa[q].w));                  \
                *(uint2*)&As[buf][r * ASTR + 4 * c] = u;                        \
            }                                                                   \
        }                                                                       \
        _Pragma("unroll")                                                       \
        for (int q = 0; q < 2; q++) {                                           \
            const int idx = q * 256 + tid;                                      \
            const int r = idx >> 2, c8 = idx & 3;                               \
            *(uint4*)&Bs[buf][r * ASTR + 8 * c8] = pb[q];                       \
        }

    LOAD_A(0); LOAD_B(0); STORE_AB(0);
    __syncthreads();

    const uint32_t aBase0 = smem_u32(&As[0][0]);
    const uint32_t bBase0 = smem_u32(&Bs[0][0]);
    const uint32_t bufStride = 128 * ASTR * 2;

    for (int kt = 0; kt < NKT; kt++) {
        const int buf = kt & 1;
        if (kt + 1 < NKT) { const int kn = (kt + 1) * 32; LOAD_A(kn); LOAD_B(kn); }

        const uint32_t aB = aBase0 + buf * bufStride;
        const uint32_t bB = bBase0 + buf * bufStride;

        #pragma unroll
        for (int ks = 0; ks < 2; ks++) {
            uint32_t af[4][4];
            #pragma unroll
            for (int mt = 0; mt < 4; mt++)
                ldm_x4(af[mt], aB + 2 * ((rowA + mt * 16) * ASTR + (2 * ks + cbA) * 8));
            #pragma unroll
            for (int g = 0; g < 2; g++) {
                uint32_t bf[4];
                ldm_x4(bf, bB + 2 * ((rowB + g * 16) * ASTR + (2 * ks + cbB) * 8));
                #pragma unroll
                for (int mt = 0; mt < 4; mt++) {
                    mma16816(acc[mt][2 * g],     af[mt], bf[0], bf[1]);
                    mma16816(acc[mt][2 * g + 1], af[mt], bf[2], bf[3]);
                }
            }
        }

        if (kt + 1 < NKT) { STORE_AB(buf ^ 1); }
        __syncthreads();
    }

    const int fr = lane >> 2;
    const int fc = lane & 3;
    #pragma unroll
    for (int mt = 0; mt < 4; mt++) {
        #pragma unroll
        for (int nt = 0; nt < 4; nt++) {
            const int n = n0 + wn * 32 + nt * 8 + 2 * fc;
            const float b0 = bias[n], b1 = bias[n + 1];
            #pragma unroll
            for (int half_ : {0, 1}) {
                const int m = m0 + wm * 64 + mt * 16 + fr + half_ * 8;
                const float v0 = acc[mt][nt][2 * half_ + 0] + b0;
                const float v1 = acc[mt][nt][2 * half_ + 1] + b1;
                if (HEADOUT) {
                    const int b  = m >> 11;
                    const int s  = m & (S_ - 1);
                    const int h  = n >> 6;
                    const int dk = n & (DK_ - 1);
                    __half2 hv = __floats2half2_rn(v0 * scale, v1 * scale);
                    *(__half2*)((__half*)Cv +
                        ((size_t)((b << 4) + h) * S_ + s) * DK_ + dk) = hv;
                } else {
                    *(float2*)((float*)Cv + (size_t)m * D_ + n) = make_float2(v0, v1);
                }
            }
        }
    }
    #undef LOAD_A
    #undef LOAD_B
    #undef STORE_AB
}

// Fused Q/K/V projection: grid.x = 24 (3 matrices x 8 n-blocks)
__global__ __launch_bounds__(256)
void gemm_qkv(const float* __restrict__ q, const float* __restrict__ k,
              const float* __restrict__ v, const __half* __restrict__ WT,
              const float* __restrict__ bq, const float* __restrict__ bk,
              const float* __restrict__ bv,
              __half* __restrict__ Qs, __half* __restrict__ Ks, __half* __restrict__ Vs)
{
    const int mat = blockIdx.x >> 3;
    const int n0 = (blockIdx.x & 7) * 128;
    const int m0 = blockIdx.y * 128;
    const float* A = (mat == 0) ? q : (mat == 1) ? k : v;
    const float* bias = (mat == 0) ? bq : (mat == 1) ? bk : bv;
    __half* C = (mat == 0) ? Qs : (mat == 1) ? Ks : Vs;
    const __half* Wt = WT + (size_t)mat * D_ * D_;
    const float scale = (mat == 0) ? QSCALE : 1.0f;
    gemm_body<false, true>(A, Wt, bias, C, scale, m0, n0);
}

// Output projection
__global__ __launch_bounds__(256)
void gemm_out(const __half* __restrict__ A, const __half* __restrict__ Wt,
              const float* __restrict__ bias, float* __restrict__ C)
{
    gemm_body<true, false>(A, Wt, bias, C, 1.0f, blockIdx.y * 128, blockIdx.x * 128);
}

// ---------------------------------------------------------------------------
// fp16 flash attention: 128 q-rows/block (8 warps x 16), 64-key tiles,
// cp.async double-buffered K/V, exp2 in f16x2 (scores already in log2 domain).
// ---------------------------------------------------------------------------
#define KSTR 72
#define KVBYTES (64 * KSTR * 2)   // 9216 bytes per tile buffer

__global__ __launch_bounds__(256, 2)
void attn_fp16(const __half* __restrict__ Qh, const __half* __restrict__ Kh,
               const __half* __restrict__ Vh, __half* __restrict__ O)
{
    __shared__ __align__(16) __half Ks[2][64 * KSTR];
    __shared__ __align__(16) __half Vs[2][64 * KSTR];

    const int tid  = threadIdx.x;
    const int lane = tid & 31;
    const int warp = tid >> 5;
    const int bh = blockIdx.y;
    const int b  = bh >> 4;
    const int h  = bh & (H_ - 1);
    const int q0 = blockIdx.x * 128;
    const int wrow = warp * 16;

    const int fr = lane >> 2;
    const int fc = lane & 3;

    // Q fragments: warp's 16 rows x 64 dk (Q pre-scaled by QSCALE)
    uint32_t qa[4][4];
    {
        const __half* qb = Qh + ((size_t)bh * S_ + q0 + wrow) * DK_;
        #pragma unroll
        for (int ks = 0; ks < 4; ks++) {
            qa[ks][0] = *(const uint32_t*)(qb + (size_t)fr * DK_ + ks * 16 + 2 * fc);
            qa[ks][1] = *(const uint32_t*)(qb + (size_t)(fr + 8) * DK_ + ks * 16 + 2 * fc);
            qa[ks][2] = *(const uint32_t*)(qb + (size_t)fr * DK_ + ks * 16 + 2 * fc + 8);
            qa[ks][3] = *(const uint32_t*)(qb + (size_t)(fr + 8) * DK_ + ks * 16 + 2 * fc + 8);
        }
    }

    float oacc[8][4];
    #pragma unroll
    for (int nt = 0; nt < 8; nt++)
        #pragma unroll
        for (int c = 0; c < 4; c++) oacc[nt][c] = 0.f;

    float m0v = -1e30f, m1v = -1e30f, l0 = 0.f, l1 = 0.f;

    const __half* kb = Kh + (size_t)bh * S_ * DK_;
    const __half* vb = Vh + (size_t)bh * S_ * DK_;

    const uint32_t ksB0 = smem_u32(&Ks[0][0]);
    const uint32_t vsB0 = smem_u32(&Vs[0][0]);

    const int rowK = (lane >> 4) * 8 + (lane & 7);
    const int cbK  = (lane >> 3) & 1;
    const int rowV = ((lane >> 3) & 1) * 8 + (lane & 7);
    const int cbV  = lane >> 4;

    // cp.async tile loader: 1024 x 16B chunks (512 K + 512 V), 4 per thread
    #define ISSUE_TILE(t, bufi)                                                 \
        _Pragma("unroll")                                                       \
        for (int qq = 0; qq < 4; qq++) {                                        \
            const int c = qq * 256 + tid;                                       \
            const int kv = c >> 9;                                              \
            const int cc = c & 511;                                             \
            const int r = cc >> 3, c8 = cc & 7;                                 \
            const __half* src = (kv ? vb : kb) + (size_t)((t) * 64 + r) * DK_ + 8 * c8; \
            const uint32_t dst = (kv ? vsB0 : ksB0) + (bufi) * KVBYTES +        \
                                 (r * KSTR + 8 * c8) * 2;                       \
            CP_ASYNC16(dst, src);                                               \
        }

    ISSUE_TILE(0, 0); CP_COMMIT();

    for (int t = 0; t < S_ / 64; t++) {
        const int buf = t & 1;
        if (t + 1 < S_ / 64) { ISSUE_TILE(t + 1, buf ^ 1); CP_COMMIT(); CP_WAIT1(); }
        else                 { CP_WAIT0(); }
        __syncthreads();

        const uint32_t ksBase = ksB0 + buf * KVBYTES;
        const uint32_t vsBase = vsB0 + buf * KVBYTES;

        // S = Q K^T (log2-domain scores)
        float sacc[8][4];
        #pragma unroll
        for (int nt = 0; nt < 8; nt++)
            #pragma unroll
            for (int c = 0; c < 4; c++) sacc[nt][c] = 0.f;

        #pragma unroll
        for (int ks = 0; ks < 4; ks++) {
            #pragma unroll
            for (int g = 0; g < 4; g++) {
                uint32_t bf[4];
                ldm_x4(bf, ksBase + 2 * ((g * 16 + rowK) * KSTR + (2 * ks + cbK) * 8));
                mma16816(sacc[2 * g],     qa[ks], bf[0], bf[1]);
                mma16816(sacc[2 * g + 1], qa[ks], bf[2], bf[3]);
            }
        }

        // online softmax in log2 domain
        float rmax0 = -1e30f, rmax1 = -1e30f;
        #pragma unroll
        for (int nt = 0; nt < 8; nt++) {
            rmax0 = fmaxf(rmax0, fmaxf(sacc[nt][0], sacc[nt][1]));
            rmax1 = fmaxf(rmax1, fmaxf(sacc[nt][2], sacc[nt][3]));
        }
        #pragma unroll
        for (int off = 1; off < 4; off <<= 1) {
            rmax0 = fmaxf(rmax0, __shfl_xor_sync(0xffffffffu, rmax0, off));
            rmax1 = fmaxf(rmax1, __shfl_xor_sync(0xffffffffu, rmax1, off));
        }
        const float mn0 = fmaxf(m0v, rmax0);
        const float mn1 = fmaxf(m1v, rmax1);
        const float f0 = exp2f(m0v - mn0);
        const float f1 = exp2f(m1v - mn1);
        m0v = mn0; m1v = mn1;

        // exp2 via f16x2 MUFU; P fragments built directly as half2 bits
        uint32_t p01[8], p23[8];
        float rs0 = 0.f, rs1 = 0.f;
        #pragma unroll
        for (int nt = 0; nt < 8; nt++) {
            __half2 e0 = h2exp2(__floats2half2_rn(sacc[nt][0] - m0v, sacc[nt][1] - m0v));
            __half2 e1 = h2exp2(__floats2half2_rn(sacc[nt][2] - m1v, sacc[nt][3] - m1v));
            float2 g0 = __half22float2(e0); rs0 += g0.x + g0.y;
            float2 g1 = __half22float2(e1); rs1 += g1.x + g1.y;
            p01[nt] = *(uint32_t*)&e0;
            p23[nt] = *(uint32_t*)&e1;
        }
        #pragma unroll
        for (int off = 1; off < 4; off <<= 1) {
            rs0 += __shfl_xor_sync(0xffffffffu, rs0, off);
            rs1 += __shfl_xor_sync(0xffffffffu, rs1, off);
        }
        l0 = l0 * f0 + rs0;
        l1 = l1 * f1 + rs1;
        #pragma unroll
        for (int nt = 0; nt < 8; nt++) {
            oacc[nt][0] *= f0; oacc[nt][1] *= f0;
            oacc[nt][2] *= f1; oacc[nt][3] *= f1;
        }

        // O += P V
        #pragma unroll
        for (int ks = 0; ks < 4; ks++) {
            uint32_t pf[4];
            pf[0] = p01[2 * ks];
            pf[1] = p23[2 * ks];
            pf[2] = p01[2 * ks + 1];
            pf[3] = p23[2 * ks + 1];
            #pragma unroll
            for (int gp = 0; gp < 4; gp++) {
                uint32_t bf[4];
                ldm_x4_t(bf, vsBase + 2 * ((ks * 16 + rowV) * KSTR + (2 * gp + cbV) * 8));
                mma16816(oacc[2 * gp],     pf, bf[0], bf[1]);
                mma16816(oacc[2 * gp + 1], pf, bf[2], bf[3]);
            }
        }
        __syncthreads();
    }

    // normalize + write half [B,S,D]
    const float inv0 = 1.f / l0;
    const float inv1 = 1.f / l1;
    __half* ob = O + ((size_t)b * S_ + q0 + wrow) * D_ + h * DK_;
    #pragma unroll
    for (int nt = 0; nt < 8; nt++) {
        *(__half2*)(ob + (size_t)fr * D_ + nt * 8 + 2 * fc) =
            __floats2half2_rn(oacc[nt][0] * inv0, oacc[nt][1] * inv0);
        *(__half2*)(ob + (size_t)(fr + 8) * D_ + nt * 8 + 2 * fc) =
            __floats2half2_rn(oacc[nt][2] * inv1, oacc[nt][3] * inv1);
    }
    #undef ISSUE_TILE
}

// ---------------------------------------------------------------------------
extern "C" void kernel_launch(void* const* d_in, const int* in_sizes, int n_in,
                              void* d_out, int out_size)
{
    const float* q  = (const float*)d_in[0];
    const float* k  = (const float*)d_in[1];
    const float* v  = (const float*)d_in[2];
    const float* wq = (const float*)d_in[3];
    const float* bq = (const float*)d_in[4];
    const float* wk = (const float*)d_in[5];
    const float* bk = (const float*)d_in[6];
    const float* wv = (const float*)d_in[7];
    const float* bv = (const float*)d_in[8];
    const float* wo = (const float*)d_in[9];
    const float* bo = (const float*)d_in[10];
    float* out = (float*)d_out;

    __half *Qs, *Ks, *Vs, *As, *WT;
    cudaGetSymbolAddress((void**)&Qs, g_Qh);
    cudaGetSymbolAddress((void**)&Ks, g_Kh);
    cudaGetSymbolAddress((void**)&Vs, g_Vh);
    cudaGetSymbolAddress((void**)&As, g_Ah);
    cudaGetSymbolAddress((void**)&WT, g_WTh);
    __half* WoT = WT + 3 * (size_t)D_ * D_;

    WPtrs wp;
    wp.in[0] = wq; wp.in[1] = wk; wp.in[2] = wv; wp.in[3] = wo;
    wp.out[0] = WT + 0 * (size_t)D_ * D_;
    wp.out[1] = WT + 1 * (size_t)D_ * D_;
    wp.out[2] = WT + 2 * (size_t)D_ * D_;
    wp.out[3] = WoT;

    transposeWh4<<<dim3(32, 32, 4), 256>>>(wp);

    gemm_qkv<<<dim3(24, M_ / 128), 256>>>(q, k, v, WT, bq, bk, bv, Qs, Ks, Vs);

    attn_fp16<<<dim3(S_ / 128, B_ * H_), 256>>>(Qs, Ks, Vs, As);

    gemm_out<<<dim3(D_ / 128, M_ / 128), 256>>>(As, WoT, bo, out);
}